// round 6
// baseline (speedup 1.0000x reference)
#include <cuda_runtime.h>
#include <cstdint>

#define N_PTS 320
#define D_DIM 64
#define P_PERMS 1000
#define NWARP (N_PTS / 32)
#define QUOTA 175   // 1750 warp-row-iterations per perm / 10 warps

// Gram matrix of the ORIGINAL data: G[a][b] = <data[a], data[b]> (409.6 KB, L2-resident)
__device__ float dG[N_PTS * N_PTS];

// ---------------------------------------------------------------------------
// Kernel 1: Gram matrix. One block per row a; thread t computes G[a][t].
// ---------------------------------------------------------------------------
__global__ __launch_bounds__(N_PTS) void gram_kernel(const float* __restrict__ data) {
    __shared__ float4 xa[D_DIM / 4];
    int a = blockIdx.x;
    int t = threadIdx.x;
    if (t < D_DIM / 4) xa[t] = reinterpret_cast<const float4*>(data)[a * (D_DIM / 4) + t];
    __syncthreads();
    const float4* xb = reinterpret_cast<const float4*>(data) + t * (D_DIM / 4);
    float acc = 0.f;
#pragma unroll
    for (int k = 0; k < D_DIM / 4; ++k) {
        float4 u = xa[k];
        float4 v = __ldg(xb + k);
        acc = fmaf(u.x, v.x, acc);
        acc = fmaf(u.y, v.y, acc);
        acc = fmaf(u.z, v.z, acc);
        acc = fmaf(u.w, v.w, acc);
    }
    dG[a * N_PTS + t] = acc;
}

// ---------------------------------------------------------------------------
// Kernel 2: one block per permutation (block 0 = identity).
//
// Original-space pair formulation (sigma is a bijection):
//   sq(a,b) = nrm_a + nrm_b - 2 sInv[a] sInv[b] G[a,b]
//   F(a,b)  = max(fsInv[a], fsInv[b])
//
// Work schedule: the upper triangle is covered by 10 column-groups of 32;
// group g needs row iterations a in [0, 32g+31). Total warp-row-iters =
// sum(32g+31) = 1750. Each warp takes EXACTLY 175 contiguous iters from the
// flattened (g, a) space (prefix S_g = 16g^2+15g), so all warps finish
// together -> no triangular tail. Lanes past the in-tile diagonal are
// predicated off (a < col) on the accumulating FFMAs only.
// ---------------------------------------------------------------------------
__global__ __launch_bounds__(N_PTS) void qet_kernel(
    const float* __restrict__ faP, const float* __restrict__ bsP,
    const int* __restrict__ types, const int* __restrict__ perms,
    float* __restrict__ out)
{
    __shared__ float4 meta[N_PTS];       // meta[a] = {sInv[a], fsInv[a], nrm_a, pad}
    __shared__ float2 sred[NWARP];

    const int p = blockIdx.x;
    const int t = threadIdx.x;

    const float fa = *faP;
    const float bs = *bsP;

    const int pj = (p == 0) ? t : perms[(p - 1) * N_PTS + t];
    const int tt = types[t];
    const int tp = types[pj];

    float s;
    if (pj == t)                 s = 1.0f;
    else if (tt == 0 && tp == 0) s = fa;
    else if (tt == 1 && tp == 1) s = bs;
    else                         s = 1.0f;

    const float fsv = (tt == 0) ? fa : bs;

    meta[pj].x = s;                      // sInv
    meta[pj].y = fsv;                    // fsInv
    meta[t].z  = dG[t * (N_PTS + 1)];    // nrm (natural index, sign-free)
    __syncthreads();

    const int wid = t >> 5, lane = t & 31;

    // locate start of this warp's 175-iteration span in flattened (g,a) space
    int idx = wid * QUOTA;
    int g = 0;
    while (idx >= 16 * (g + 1) * (g + 1) + 15 * (g + 1)) ++g;   // S_{g+1} <= idx ?
    int a = idx - (16 * g * g + 15 * g);
    int rem = QUOTA;

    float accv = 0.f;   // sum of F*val
    float accd = 0.f;   // sum of val^2 (F^2 == 1)

    while (rem > 0) {
        const int   col = (g << 5) + lane;
        const float4 mc = meta[col];
        const float m2  = -2.0f * mc.x;
        const float pn  = mc.z;
        const float fcl = mc.y;
        const float* gp = dG + col + a * N_PTS;
        const int   Lg  = (g << 5) + 31;
        int trips = Lg - a;
        if (trips > rem) trips = rem;
        rem -= trips;
        int act = col - a;               // active iff k < act  (a+k < col)

#pragma unroll 8
        for (int k = 0; k < trips; ++k) {
            float4 ma = meta[a + k];             // broadcast LDS.128
            float gv  = __ldg(gp + k * N_PTS);   // coalesced LDG
            float sg  = ma.x * gv;
            float ns  = pn + ma.z;
            float d2  = fmaf(m2, sg, ns);
            d2 = fmaxf(d2, 0.0f);
            float v;
            asm("sqrt.approx.f32 %0, %1;" : "=f"(v) : "f"(d2));
            float fm = fmaxf(fcl, ma.y);
            if (k < act) {                       // predicated accumulate
                accv = fmaf(fm, v, accv);
                accd = fmaf(v, v, accd);
            }
        }
        a = 0;
        ++g;
    }

    // block reduction (10 warps)
#pragma unroll
    for (int o = 16; o; o >>= 1) {
        accv += __shfl_down_sync(0xffffffffu, accv, o);
        accd += __shfl_down_sync(0xffffffffu, accd, o);
    }
    if (lane == 0) sred[wid] = make_float2(accv, accd);
    __syncthreads();
    if (t == 0) {
        double Sv = 0.0, Sd = 0.0;
#pragma unroll
        for (int w2 = 0; w2 < NWARP; ++w2) { Sv += sred[w2].x; Sd += sred[w2].y; }
        const double M = (double)(N_PTS * (N_PTS - 1) / 2);   // 51040
        out[p] = (float)((Sd - Sv * Sv / M) / (M - 1.0));
    }
}

// ---------------------------------------------------------------------------
// inputs: data[320*64] f32, fermion_antisymmetry f32[1], boson_symmetry f32[1],
// particle_types i32[320], perms i32[1000*320]; output: stats f32[1001]
// ---------------------------------------------------------------------------
extern "C" void kernel_launch(void* const* d_in, const int* in_sizes, int n_in,
                              void* d_out, int out_size) {
    const float* data  = (const float*)d_in[0];
    const float* fa    = (const float*)d_in[1];
    const float* bs    = (const float*)d_in[2];
    const int*   types = (const int*)d_in[3];
    const int*   perms = (const int*)d_in[4];
    float*       out   = (float*)d_out;

    gram_kernel<<<N_PTS, N_PTS>>>(data);
    qet_kernel<<<P_PERMS + 1, N_PTS>>>(fa, bs, types, perms, out);
}

// round 7
// speedup vs baseline: 1.6283x; 1.6283x over previous
#include <cuda_runtime.h>
#include <cstdint>

#define N_PTS 320
#define D_DIM 64
#define P_PERMS 1000
#define NWARP (N_PTS / 32)
#define NPERM (P_PERMS + 1)          // 1001 (perm 0 = identity)
#define NBLK  ((NPERM + 1) / 2)      // 501

// Gram matrix of the ORIGINAL data: G[a][b] = <data[a], data[b]> (409.6 KB, L2-resident)
__device__ float dG[N_PTS * N_PTS];

// ---------------------------------------------------------------------------
// Kernel 1: Gram matrix. One block per row a; thread t computes G[a][t].
// ---------------------------------------------------------------------------
__global__ __launch_bounds__(N_PTS) void gram_kernel(const float* __restrict__ data) {
    __shared__ float4 xa[D_DIM / 4];
    int a = blockIdx.x;
    int t = threadIdx.x;
    if (t < D_DIM / 4) xa[t] = reinterpret_cast<const float4*>(data)[a * (D_DIM / 4) + t];
    __syncthreads();
    const float4* xb = reinterpret_cast<const float4*>(data) + t * (D_DIM / 4);
    float acc = 0.f;
#pragma unroll
    for (int k = 0; k < D_DIM / 4; ++k) {
        float4 u = xa[k];
        float4 v = __ldg(xb + k);
        acc = fmaf(u.x, v.x, acc);
        acc = fmaf(u.y, v.y, acc);
        acc = fmaf(u.z, v.z, acc);
        acc = fmaf(u.w, v.w, acc);
    }
    dG[a * N_PTS + t] = acc;
}

// ---------------------------------------------------------------------------
// Kernel 2: each block handles TWO permutations (pA = 2b, pB = 2b+1).
//
// Original-space pair formulation (sigma is a bijection):
//   sq(a,b) = nrm_a + nrm_b - 2 sInv[a] sInv[b] G[a,b]
//   F(a,b)  = max(fsInv[a], fsInv[b])
//
// Balance trick: warp w takes column-group w of perm A and column-group
// (9-w) of perm B -> every warp runs (32w+31)+(32(9-w)+31) = 350 row-trips.
// Exact intra-block balance with the ORIGINAL cheap static-shape loop body
// (no dynamic segmentation, no extra predicates).
// ---------------------------------------------------------------------------
__device__ __forceinline__ void setup_meta(
    float4* meta, int p, int t, float fa, float bs,
    const int* __restrict__ types, const int* __restrict__ perms)
{
    const int pj = (p == 0) ? t : perms[(p - 1) * N_PTS + t];
    const int tt = types[t];
    const int tp = types[pj];
    float s;
    if (pj == t)                 s = 1.0f;
    else if (tt == 0 && tp == 0) s = fa;
    else if (tt == 1 && tp == 1) s = bs;
    else                         s = 1.0f;
    const float fsv = (tt == 0) ? fa : bs;
    meta[pj].x = s;                      // sInv
    meta[pj].y = fsv;                    // fsInv
    meta[t].z  = dG[t * (N_PTS + 1)];    // nrm (natural index, sign-free)
}

__device__ __forceinline__ void triangle_col(
    const float4* __restrict__ meta, int col, float& accv, float& accd)
{
    const float4 mc = meta[col];
    const float m2  = -2.0f * mc.x;
    const float pn  = mc.z;
    const float fcl = mc.y;
    const float* gcol = dG + col;
#pragma unroll 4
    for (int a = 0; a < col; ++a) {
        float4 ma = meta[a];                  // broadcast LDS.128
        float gv  = __ldg(gcol + a * N_PTS);  // coalesced LDG (1 line / warp)
        float sg  = ma.x * gv;
        float ns  = pn + ma.z;
        float d2  = fmaf(m2, sg, ns);
        d2 = fmaxf(d2, 0.0f);
        float v;
        asm("sqrt.approx.f32 %0, %1;" : "=f"(v) : "f"(d2));
        float fm = fmaxf(fcl, ma.y);
        accv = fmaf(fm, v, accv);
        accd = fmaf(v, v, accd);
    }
}

__global__ __launch_bounds__(N_PTS) void qet_kernel(
    const float* __restrict__ faP, const float* __restrict__ bsP,
    const int* __restrict__ types, const int* __restrict__ perms,
    float* __restrict__ out)
{
    __shared__ float4 metaA[N_PTS];
    __shared__ float4 metaB[N_PTS];
    __shared__ float2 sredA[NWARP];
    __shared__ float2 sredB[NWARP];

    const int b  = blockIdx.x;
    const int t  = threadIdx.x;
    const int pA = 2 * b;
    const int pB = 2 * b + 1;
    const bool hasB = (pB < NPERM);

    const float fa = *faP;
    const float bs = *bsP;

    setup_meta(metaA, pA, t, fa, bs, types, perms);
    if (hasB) setup_meta(metaB, pB, t, fa, bs, types, perms);
    __syncthreads();

    const int wid = t >> 5, lane = t & 31;

    float accvA = 0.f, accdA = 0.f;
    float accvB = 0.f, accdB = 0.f;

    // perm A: column-group wid; perm B: column-group (NWARP-1 - wid)
    triangle_col(metaA, (wid << 5) + lane, accvA, accdA);
    if (hasB) triangle_col(metaB, ((NWARP - 1 - wid) << 5) + lane, accvB, accdB);

    // reductions (10 warps)
#pragma unroll
    for (int o = 16; o; o >>= 1) {
        accvA += __shfl_down_sync(0xffffffffu, accvA, o);
        accdA += __shfl_down_sync(0xffffffffu, accdA, o);
        accvB += __shfl_down_sync(0xffffffffu, accvB, o);
        accdB += __shfl_down_sync(0xffffffffu, accdB, o);
    }
    if (lane == 0) {
        sredA[wid] = make_float2(accvA, accdA);
        sredB[wid] = make_float2(accvB, accdB);
    }
    __syncthreads();
    if (t == 0) {
        const double M = (double)(N_PTS * (N_PTS - 1) / 2);   // 51040
        double Sv = 0.0, Sd = 0.0;
#pragma unroll
        for (int w2 = 0; w2 < NWARP; ++w2) { Sv += sredA[w2].x; Sd += sredA[w2].y; }
        out[pA] = (float)((Sd - Sv * Sv / M) / (M - 1.0));
        if (hasB) {
            Sv = 0.0; Sd = 0.0;
#pragma unroll
            for (int w2 = 0; w2 < NWARP; ++w2) { Sv += sredB[w2].x; Sd += sredB[w2].y; }
            out[pB] = (float)((Sd - Sv * Sv / M) / (M - 1.0));
        }
    }
}

// ---------------------------------------------------------------------------
// inputs: data[320*64] f32, fermion_antisymmetry f32[1], boson_symmetry f32[1],
// particle_types i32[320], perms i32[1000*320]; output: stats f32[1001]
// ---------------------------------------------------------------------------
extern "C" void kernel_launch(void* const* d_in, const int* in_sizes, int n_in,
                              void* d_out, int out_size) {
    const float* data  = (const float*)d_in[0];
    const float* fa    = (const float*)d_in[1];
    const float* bs    = (const float*)d_in[2];
    const int*   types = (const int*)d_in[3];
    const int*   perms = (const int*)d_in[4];
    float*       out   = (float*)d_out;

    gram_kernel<<<N_PTS, N_PTS>>>(data);
    qet_kernel<<<NBLK, N_PTS>>>(fa, bs, types, perms, out);
}